// round 14
// baseline (speedup 1.0000x reference)
#include <cuda_runtime.h>
#include <cuda_bf16.h>
#include <cstdint>

// MultiDense via mma.sync: per i, D[j=32, l=128] = x @ W^T + bias, split-bf16
// 3-pass (AhBh + AhBl + AlBh), fp32 accum. One CTA (128 thr) per i.
// R14: x loads folded into the unrolled MMA loop (ptxas pipelines them),
// W staging uses quad mapping + STS.64. 3 CTAs/SM.

#define I_DIM 8192
#define J_DIM 32
#define IN_F  128
#define OUT_F 128
#define NODE_MASK 4095
#define PROW_SRC 129
#define W_SRC_FLOATS (OUT_F * PROW_SRC)     // 16512

#define RSTRIDE 136                          // bf16 row stride (272B): ldmatrix conflict-free
#define OFF_WHI 0                            // 128 x 136 bf16 = 34816
#define OFF_WLO 34816
#define OFF_BIAS 69632                       // 128 f32
#define SMEM_BYTES 70144                     // 3 CTAs/SM

__device__ __forceinline__ uint32_t smem_u32(const void* p) {
    uint32_t a;
    asm("{ .reg .u64 t; cvta.to.shared.u64 t, %1; cvt.u32.u64 %0, t; }" : "=r"(a) : "l"(p));
    return a;
}

__device__ __forceinline__ void ldmx4(uint32_t* r, uint32_t addr) {
    asm volatile("ldmatrix.sync.aligned.m8n8.x4.shared.b16 {%0,%1,%2,%3}, [%4];"
                 : "=r"(r[0]), "=r"(r[1]), "=r"(r[2]), "=r"(r[3]) : "r"(addr));
}

__device__ __forceinline__ void mma_bf16(float* c, uint32_t a0, uint32_t a1, uint32_t a2,
                                         uint32_t a3, uint32_t b0, uint32_t b1) {
    asm volatile(
        "mma.sync.aligned.m16n8k16.row.col.f32.bf16.bf16.f32 "
        "{%0,%1,%2,%3}, {%4,%5,%6,%7}, {%8,%9}, {%0,%1,%2,%3};"
        : "+f"(c[0]), "+f"(c[1]), "+f"(c[2]), "+f"(c[3])
        : "r"(a0), "r"(a1), "r"(a2), "r"(a3), "r"(b0), "r"(b1));
}

__device__ __forceinline__ uint32_t cvt_hi(float2 v) {
    __nv_bfloat162 h;
    h.x = __float2bfloat16(v.x);
    h.y = __float2bfloat16(v.y);
    return *reinterpret_cast<uint32_t*>(&h);
}
__device__ __forceinline__ uint32_t cvt_lo(float2 v, uint32_t hi) {
    __nv_bfloat162 h = *reinterpret_cast<__nv_bfloat162*>(&hi);
    __nv_bfloat162 l;
    l.x = __float2bfloat16(v.x - __bfloat162float(h.x));
    l.y = __float2bfloat16(v.y - __bfloat162float(h.y));
    return *reinterpret_cast<uint32_t*>(&l);
}

__global__ __launch_bounds__(128, 3)
void multidense_kernel(const float* __restrict__ x_in,
                       const int* __restrict__ inds,
                       const float* __restrict__ params,
                       float* __restrict__ out)
{
    extern __shared__ char smem[];
    const uint32_t sb = smem_u32(smem);
    float* bias_s = reinterpret_cast<float*>(smem + OFF_BIAS);

    const int i = blockIdx.x;
    const int t = threadIdx.x;            // 0..127
    const int node = inds[i] & NODE_MASK;

    // ---- stage + split W: quad mapping, batched LDG, STS.64 ----
    // quad q-index pidx: l = pidx>>5, kq = (pidx&31)*4 (4 floats, same row)
    {
        const float* pg = params + (size_t)node * W_SRC_FLOATS;
        #pragma unroll
        for (int qb = 0; qb < 4; qb++) {
            float v[8][4];
            int lv[8], kv[8];
            #pragma unroll
            for (int m = 0; m < 8; m++) {
                int pidx = t + 128 * (qb * 8 + m);       // 0..4095
                lv[m] = pidx >> 5;
                kv[m] = (pidx & 31) * 4;
                const float* s = pg + lv[m] * PROW_SRC + kv[m];
                v[m][0] = s[0]; v[m][1] = s[1];          // 32 LDGs in flight
                v[m][2] = s[2]; v[m][3] = s[3];
            }
            #pragma unroll
            for (int m = 0; m < 8; m++) {
                float2 p0 = make_float2(v[m][0], v[m][1]);
                float2 p1 = make_float2(v[m][2], v[m][3]);
                uint32_t h0 = cvt_hi(p0), h1 = cvt_hi(p1);
                uint32_t l0 = cvt_lo(p0, h0), l1 = cvt_lo(p1, h1);
                uint32_t o = (uint32_t)(lv[m] * RSTRIDE + kv[m]) * 2;   // 8B-aligned
                uint2 hp; hp.x = h0; hp.y = h1;
                uint2 lp; lp.x = l0; lp.y = l1;
                *reinterpret_cast<uint2*>(smem + OFF_WHI + o) = hp;
                *reinterpret_cast<uint2*>(smem + OFF_WLO + o) = lp;
            }
        }
        bias_s[t] = pg[t * PROW_SRC + IN_F];
    }

    const int wid = t >> 5, lane = t & 31;
    const int j0 = (wid >> 1) * 16;
    const int l0 = (wid & 1) * 64;
    const int g = lane >> 2, tg = lane & 3;

    // x row pointers for this thread's A fragments
    const float* xg = x_in + (size_t)i * (J_DIM * IN_F);
    const float* r0p = xg + (j0 + g) * IN_F + 2 * tg;
    const float* r1p = xg + (j0 + 8 + g) * IN_F + 2 * tg;

    __syncthreads();                       // W planes ready

    // ---- compute: warp -> j-rows [j0,j0+16) x l-cols [l0,l0+64) ----
    float c[8][4];
    #pragma unroll
    for (int nt = 0; nt < 8; nt++)
        #pragma unroll
        for (int q = 0; q < 4; q++) c[nt][q] = 0.0f;

    // ldmatrix B lane->row map (tiles: (n0-7,k0)(n0-7,k8)(n8-15,k0)(n8-15,k8))
    const int brow  = l0 + (lane & 7) + (lane >> 4) * 8;
    const int bkoff = ((lane >> 3) & 1) * 8;
    uint32_t b_hi = sb + OFF_WHI + (uint32_t)(brow * RSTRIDE + bkoff) * 2;
    uint32_t b_lo = sb + OFF_WLO + (uint32_t)(brow * RSTRIDE + bkoff) * 2;
    const uint32_t PSTEP = 16 * RSTRIDE * 2;

    #pragma unroll
    for (int ks = 0; ks < 8; ks++) {
        const uint32_t ko = (uint32_t)ks * 32;

        // x fragments for this ks (ptxas hoists these LDGs across iterations)
        const float2 u00 = *reinterpret_cast<const float2*>(r0p + 16 * ks);      // (g,   klo)
        const float2 u10 = *reinterpret_cast<const float2*>(r1p + 16 * ks);      // (g+8, klo)
        const float2 u01 = *reinterpret_cast<const float2*>(r0p + 16 * ks + 8);  // (g,   khi)
        const float2 u11 = *reinterpret_cast<const float2*>(r1p + 16 * ks + 8);  // (g+8, khi)
        const uint32_t ah0 = cvt_hi(u00), al0 = cvt_lo(u00, ah0);
        const uint32_t ah1 = cvt_hi(u10), al1 = cvt_lo(u10, ah1);
        const uint32_t ah2 = cvt_hi(u01), al2 = cvt_lo(u01, ah2);
        const uint32_t ah3 = cvt_hi(u11), al3 = cvt_lo(u11, ah3);

        uint32_t bh[4][4], bl[4][4];
        #pragma unroll
        for (int p = 0; p < 4; p++) {
            ldmx4(bh[p], b_hi + p * PSTEP + ko);
            ldmx4(bl[p], b_lo + p * PSTEP + ko);
        }

        #pragma unroll
        for (int nt = 0; nt < 8; nt++) {
            const int p = nt >> 1;
            const int q = (nt & 1) * 2;
            mma_bf16(c[nt], ah0, ah1, ah2, ah3, bh[p][q], bh[p][q + 1]);   // hi*hi
            mma_bf16(c[nt], ah0, ah1, ah2, ah3, bl[p][q], bl[p][q + 1]);   // hi*lo
            mma_bf16(c[nt], al0, al1, al2, al3, bh[p][q], bh[p][q + 1]);   // lo*hi
        }
    }

    // ---- epilogue (verified): c0,c1 -> row j0+g; c2,c3 -> row j0+g+8 ----
    float* og = out + (size_t)i * (J_DIM * OUT_F);
    #pragma unroll
    for (int nt = 0; nt < 8; nt++) {
        const int l = l0 + nt * 8 + 2 * tg;
        const float2 b2 = *reinterpret_cast<const float2*>(bias_s + l);
        float2 r0; r0.x = c[nt][0] + b2.x; r0.y = c[nt][1] + b2.y;
        float2 r1; r1.x = c[nt][2] + b2.x; r1.y = c[nt][3] + b2.y;
        *reinterpret_cast<float2*>(og + (j0 + g)     * OUT_F + l) = r0;
        *reinterpret_cast<float2*>(og + (j0 + g + 8) * OUT_F + l) = r1;
    }
}

extern "C" void kernel_launch(void* const* d_in, const int* in_sizes, int n_in,
                              void* d_out, int out_size)
{
    const float* x_in   = (const float*)d_in[0];
    const int*   inds   = (const int*)d_in[1];
    const float* params = (const float*)d_in[2];
    float*       out    = (float*)d_out;

    static bool attr_set = false;
    if (!attr_set) {
        cudaFuncSetAttribute(multidense_kernel,
                             cudaFuncAttributeMaxDynamicSharedMemorySize, SMEM_BYTES);
        attr_set = true;
    }

    multidense_kernel<<<I_DIM, 128, SMEM_BYTES>>>(x_in, inds, params, out);
}